// round 5
// baseline (speedup 1.0000x reference)
#include <cuda_runtime.h>

// Problem constants
#define BB 2
#define SS 4096
#define DD 512
#define HH 8
#define DKK 64
#define MM (BB*SS)        // 8192 rows
#define SWW (SS/32)       // 128 mask words per row

// Scratch (device globals; no runtime allocation allowed)
__device__ float g_Qh[MM*DD];        // head-split [ (b*H+h), s, dk ]
__device__ float g_Kh[MM*DD];
__device__ float g_Vh[MM*DD];
__device__ float g_X [MM*DD];        // attention output, [b, s, d]
__device__ unsigned g_mbits[BB*SS*SWW];  // bit-packed mask

// ---------------------------------------------------------------------------
// Pack int32 mask (0/1) into bits: mbits[(b*S+q)*SW + k/32], bit k%32
// ---------------------------------------------------------------------------
__global__ __launch_bounds__(256) void pack_mask(const int* __restrict__ mask,
                                                 unsigned* __restrict__ mb) {
    int gid = blockIdx.x * 256 + threadIdx.x;
    int bit = mask[gid] != 0;
    unsigned w = __ballot_sync(0xffffffffu, bit);
    if ((threadIdx.x & 31) == 0) mb[gid >> 5] = w;
}

// ---------------------------------------------------------------------------
// C[M x 512] = A[M x 512] * W[512 x 512], 64x64 CTA tile, BK=16, 4x4/thread.
// split=1: write head-split layout [(b*H+h), s, dk]; split=0: plain row-major.
// ---------------------------------------------------------------------------
__global__ __launch_bounds__(256) void gemm512(const float* __restrict__ A,
                                               const float* __restrict__ W,
                                               float* __restrict__ C,
                                               int split) {
    __shared__ float As[64*17];
    __shared__ float Ws[16*64];
    const int m0 = blockIdx.x * 64;
    const int n0 = blockIdx.y * 64;
    const int tid = threadIdx.x;
    const int ty = tid >> 4, tx = tid & 15;
    const int ar = tid >> 2, ac = (tid & 3) * 4;
    const int wr = tid >> 4, wc = (tid & 15) * 4;

    float c[4][4];
#pragma unroll
    for (int i = 0; i < 4; i++)
#pragma unroll
        for (int j = 0; j < 4; j++) c[i][j] = 0.f;

    for (int k0 = 0; k0 < 512; k0 += 16) {
        float4 av = *(const float4*)(A + (size_t)(m0 + ar) * 512 + k0 + ac);
        float4 wv = *(const float4*)(W + (size_t)(k0 + wr) * 512 + n0 + wc);
        __syncthreads();
        As[ar*17 + ac + 0] = av.x;
        As[ar*17 + ac + 1] = av.y;
        As[ar*17 + ac + 2] = av.z;
        As[ar*17 + ac + 3] = av.w;
        *(float4*)&Ws[wr*64 + wc] = wv;
        __syncthreads();
#pragma unroll
        for (int kk = 0; kk < 16; kk++) {
            float a0 = As[(ty*4+0)*17 + kk];
            float a1 = As[(ty*4+1)*17 + kk];
            float a2 = As[(ty*4+2)*17 + kk];
            float a3 = As[(ty*4+3)*17 + kk];
            float4 bv = *(const float4*)&Ws[kk*64 + tx*4];
            c[0][0] += a0*bv.x; c[0][1] += a0*bv.y; c[0][2] += a0*bv.z; c[0][3] += a0*bv.w;
            c[1][0] += a1*bv.x; c[1][1] += a1*bv.y; c[1][2] += a1*bv.z; c[1][3] += a1*bv.w;
            c[2][0] += a2*bv.x; c[2][1] += a2*bv.y; c[2][2] += a2*bv.z; c[2][3] += a2*bv.w;
            c[3][0] += a3*bv.x; c[3][1] += a3*bv.y; c[3][2] += a3*bv.z; c[3][3] += a3*bv.w;
        }
    }

    if (split) {
        const int h = (int)blockIdx.y;   // 64-wide col tile == one head
#pragma unroll
        for (int i = 0; i < 4; i++) {
            int m = m0 + ty*4 + i;
            int b = m >> 12, s = m & 4095;
            float4 o = make_float4(c[i][0], c[i][1], c[i][2], c[i][3]);
            *(float4*)(C + ((size_t)((b*HH + h)*SS + s))*DKK + tx*4) = o;
        }
    } else {
#pragma unroll
        for (int i = 0; i < 4; i++) {
            int m = m0 + ty*4 + i;
            float4 o = make_float4(c[i][0], c[i][1], c[i][2], c[i][3]);
            *(float4*)(C + (size_t)m*512 + n0 + tx*4) = o;
        }
    }
}

// ---------------------------------------------------------------------------
// Flash attention: grid (S/64 q-tiles, B*H). 64x64 tiles, online softmax.
// Thread (ty,tx): S rows ty*4..+3, S cols {tx, tx+16, tx+32, tx+48},
//                 O cols tx*4..+3 (dk).
// ---------------------------------------------------------------------------
__global__ __launch_bounds__(256) void flash_attn(const float* __restrict__ Qh,
                                                  const float* __restrict__ Kh,
                                                  const float* __restrict__ Vh,
                                                  const unsigned* __restrict__ mb,
                                                  float* __restrict__ X) {
    extern __shared__ float sm[];
    float* Qs = sm;               // 64 x 65
    float* Ks = Qs + 64*65;       // 64 x 65
    float* Vs = Ks + 64*65;       // 64 x 64
    float* Ps = Vs + 64*64;       // 64 x 65

    const int qt = blockIdx.x;
    const int bh = blockIdx.y;
    const int b  = bh >> 3, h = bh & 7;
    const float* Qp = Qh + ((size_t)bh*SS + qt*64) * DKK;
    const float* Kp = Kh + (size_t)bh*SS*DKK;
    const float* Vp = Vh + (size_t)bh*SS*DKK;
    const unsigned* mrow = mb + ((size_t)b*SS + qt*64) * SWW;

    const int tid = threadIdx.x;
    const int ty = tid >> 4, tx = tid & 15;

    // Load Q tile (64x64) into padded smem
#pragma unroll
    for (int p = 0; p < 4; p++) {
        int idx = tid + p*256;
        int r = idx >> 4, cc = (idx & 15) * 4;
        float4 v = *(const float4*)(Qp + r*DKK + cc);
        Qs[r*65+cc+0] = v.x; Qs[r*65+cc+1] = v.y;
        Qs[r*65+cc+2] = v.z; Qs[r*65+cc+3] = v.w;
    }

    float mx[4], ls[4], acc[4][4];
#pragma unroll
    for (int i = 0; i < 4; i++) {
        mx[i] = -1e30f; ls[i] = 0.f;
#pragma unroll
        for (int j = 0; j < 4; j++) acc[i][j] = 0.f;
    }
    const float scale = 0.125f;   // 1/sqrt(64)

    for (int kt = 0; kt < SS/64; kt++) {
        __syncthreads();   // protect Ks/Vs/Ps from previous iteration's readers
#pragma unroll
        for (int p = 0; p < 4; p++) {
            int idx = tid + p*256;
            int r = idx >> 4, cc = (idx & 15) * 4;
            float4 kv = *(const float4*)(Kp + (size_t)(kt*64 + r)*DKK + cc);
            Ks[r*65+cc+0] = kv.x; Ks[r*65+cc+1] = kv.y;
            Ks[r*65+cc+2] = kv.z; Ks[r*65+cc+3] = kv.w;
            float4 vv = *(const float4*)(Vp + (size_t)(kt*64 + r)*DKK + cc);
            *(float4*)&Vs[r*64+cc] = vv;
        }
        __syncthreads();

        // S = Q * K^T (64x64x64)
        float sacc[4][4];
#pragma unroll
        for (int i = 0; i < 4; i++)
#pragma unroll
            for (int j = 0; j < 4; j++) sacc[i][j] = 0.f;

#pragma unroll 8
        for (int kk = 0; kk < 64; kk++) {
            float a0 = Qs[(ty*4+0)*65 + kk];
            float a1 = Qs[(ty*4+1)*65 + kk];
            float a2 = Qs[(ty*4+2)*65 + kk];
            float a3 = Qs[(ty*4+3)*65 + kk];
            float b0 = Ks[(tx     )*65 + kk];
            float b1 = Ks[(tx + 16)*65 + kk];
            float b2 = Ks[(tx + 32)*65 + kk];
            float b3 = Ks[(tx + 48)*65 + kk];
            sacc[0][0] += a0*b0; sacc[0][1] += a0*b1; sacc[0][2] += a0*b2; sacc[0][3] += a0*b3;
            sacc[1][0] += a1*b0; sacc[1][1] += a1*b1; sacc[1][2] += a1*b2; sacc[1][3] += a1*b3;
            sacc[2][0] += a2*b0; sacc[2][1] += a2*b1; sacc[2][2] += a2*b2; sacc[2][3] += a2*b3;
            sacc[3][0] += a3*b0; sacc[3][1] += a3*b1; sacc[3][2] += a3*b2; sacc[3][3] += a3*b3;
        }

        // Mask + online softmax (rows ty*4+i; cols tx+16j)
#pragma unroll
        for (int i = 0; i < 4; i++) {
            int row = ty*4 + i;
            unsigned wa = mrow[row*SWW + kt*2 + 0];
            unsigned wb = mrow[row*SWW + kt*2 + 1];
            float s0 = ((wa >> tx)      & 1u) ? sacc[i][0]*scale : -1e9f;
            float s1 = ((wa >> (tx+16)) & 1u) ? sacc[i][1]*scale : -1e9f;
            float s2 = ((wb >> tx)      & 1u) ? sacc[i][2]*scale : -1e9f;
            float s3 = ((wb >> (tx+16)) & 1u) ? sacc[i][3]*scale : -1e9f;
            float rmax = fmaxf(fmaxf(s0, s1), fmaxf(s2, s3));
#pragma unroll
            for (int o = 8; o > 0; o >>= 1)
                rmax = fmaxf(rmax, __shfl_xor_sync(0xffffffffu, rmax, o));
            float mnew = fmaxf(mx[i], rmax);
            float corr = __expf(mx[i] - mnew);
            float p0 = __expf(s0 - mnew);
            float p1 = __expf(s1 - mnew);
            float p2 = __expf(s2 - mnew);
            float p3 = __expf(s3 - mnew);
            float rs = p0 + p1 + p2 + p3;
#pragma unroll
            for (int o = 8; o > 0; o >>= 1)
                rs += __shfl_xor_sync(0xffffffffu, rs, o);
            ls[i] = ls[i]*corr + rs;
            mx[i] = mnew;
#pragma unroll
            for (int j = 0; j < 4; j++) acc[i][j] *= corr;
            Ps[row*65 + tx     ] = p0;
            Ps[row*65 + tx + 16] = p1;
            Ps[row*65 + tx + 32] = p2;
            Ps[row*65 + tx + 48] = p3;
        }
        __syncthreads();

        // O += P * V (64x64x64), O cols = dk = tx*4..+3
#pragma unroll 8
        for (int kk = 0; kk < 64; kk++) {
            float4 bv = *(const float4*)&Vs[kk*64 + tx*4];
            float a0 = Ps[(ty*4+0)*65 + kk];
            float a1 = Ps[(ty*4+1)*65 + kk];
            float a2 = Ps[(ty*4+2)*65 + kk];
            float a3 = Ps[(ty*4+3)*65 + kk];
            acc[0][0] += a0*bv.x; acc[0][1] += a0*bv.y; acc[0][2] += a0*bv.z; acc[0][3] += a0*bv.w;
            acc[1][0] += a1*bv.x; acc[1][1] += a1*bv.y; acc[1][2] += a1*bv.z; acc[1][3] += a1*bv.w;
            acc[2][0] += a2*bv.x; acc[2][1] += a2*bv.y; acc[2][2] += a2*bv.z; acc[2][3] += a2*bv.w;
            acc[3][0] += a3*bv.x; acc[3][1] += a3*bv.y; acc[3][2] += a3*bv.z; acc[3][3] += a3*bv.w;
        }
    }

    // Epilogue: normalize and write X[b, s, h*64+dk]
#pragma unroll
    for (int i = 0; i < 4; i++) {
        int row = qt*64 + ty*4 + i;
        float inv = 1.0f / ls[i];
        float4 o = make_float4(acc[i][0]*inv, acc[i][1]*inv, acc[i][2]*inv, acc[i][3]*inv);
        *(float4*)(X + ((size_t)(b*SS + row))*DD + h*DKK + tx*4) = o;
    }
}

// ---------------------------------------------------------------------------
extern "C" void kernel_launch(void* const* d_in, const int* in_sizes, int n_in,
                              void* d_out, int out_size) {
    const float* q    = (const float*)d_in[0];
    const float* k    = (const float*)d_in[1];
    const float* v    = (const float*)d_in[2];
    const int*   mask = (const int*)  d_in[3];
    const float* wq   = (const float*)d_in[4];
    const float* wk   = (const float*)d_in[5];
    const float* wv   = (const float*)d_in[6];
    const float* wo   = (const float*)d_in[7];
    float* out = (float*)d_out;

    float *Qh, *Kh, *Vh, *X;
    unsigned* mbp;
    cudaGetSymbolAddress((void**)&Qh,  g_Qh);
    cudaGetSymbolAddress((void**)&Kh,  g_Kh);
    cudaGetSymbolAddress((void**)&Vh,  g_Vh);
    cudaGetSymbolAddress((void**)&X,   g_X);
    cudaGetSymbolAddress((void**)&mbp, g_mbits);

    pack_mask<<<(BB*SS*SS)/256, 256>>>(mask, mbp);

    dim3 gg(MM/64, DD/64);
    gemm512<<<gg, 256>>>(q, wq, Qh, 1);
    gemm512<<<gg, 256>>>(k, wk, Kh, 1);
    gemm512<<<gg, 256>>>(v, wv, Vh, 1);

    const int FS = (64*65 + 64*65 + 64*64 + 64*65) * 4;  // 66304 B
    cudaFuncSetAttribute(flash_attn, cudaFuncAttributeMaxDynamicSharedMemorySize, FS);
    flash_attn<<<dim3(SS/64, BB*HH), 256, FS>>>(Qh, Kh, Vh, mbp, X);

    gemm512<<<gg, 256>>>(X, wo, out, 0);
}

// round 6
// speedup vs baseline: 2.8816x; 2.8816x over previous
#include <cuda_runtime.h>
#include <cuda_fp16.h>

// Problem constants
#define BB 2
#define SS 4096
#define DD 512
#define HH 8
#define DKK 64
#define MM (BB*SS)        // 8192 rows
#define SWW (SS/32)       // 128 mask words per row

// Scratch (device globals; no runtime allocation allowed)
__device__ __half g_Qh[MM*DD];       // head-split [(b*H+h), s, dk], fp16
__device__ __half g_Kh[MM*DD];
__device__ __half g_Vh[MM*DD];
__device__ float  g_X [MM*DD];       // attention output, [b, s, d], fp32
__device__ unsigned g_mbits[BB*SS*SWW];  // bit-packed mask

// ---------------------------------------------------------------------------
// Pack int32 mask (0/1) into bits
// ---------------------------------------------------------------------------
__global__ __launch_bounds__(256) void pack_mask(const int* __restrict__ mask,
                                                 unsigned* __restrict__ mb) {
    int gid = blockIdx.x * 256 + threadIdx.x;
    int bit = mask[gid] != 0;
    unsigned w = __ballot_sync(0xffffffffu, bit);
    if ((threadIdx.x & 31) == 0) mb[gid >> 5] = w;
}

// ---------------------------------------------------------------------------
// C[M x 512] = A[M x 512] * W[512 x 512], fp32 SIMT (projections + out proj).
// split=1: write HALF output in head-split layout; split=0: fp32 row-major.
// ---------------------------------------------------------------------------
__global__ __launch_bounds__(256) void gemm512(const float* __restrict__ A,
                                               const float* __restrict__ W,
                                               float* __restrict__ Cf,
                                               __half* __restrict__ Ch,
                                               int split) {
    __shared__ float As[64*17];
    __shared__ float Ws[16*64];
    const int m0 = blockIdx.x * 64;
    const int n0 = blockIdx.y * 64;
    const int tid = threadIdx.x;
    const int ty = tid >> 4, tx = tid & 15;
    const int ar = tid >> 2, ac = (tid & 3) * 4;
    const int wr = tid >> 4, wc = (tid & 15) * 4;

    float c[4][4];
#pragma unroll
    for (int i = 0; i < 4; i++)
#pragma unroll
        for (int j = 0; j < 4; j++) c[i][j] = 0.f;

    for (int k0 = 0; k0 < 512; k0 += 16) {
        float4 av = *(const float4*)(A + (size_t)(m0 + ar) * 512 + k0 + ac);
        float4 wv = *(const float4*)(W + (size_t)(k0 + wr) * 512 + n0 + wc);
        __syncthreads();
        As[ar*17 + ac + 0] = av.x;
        As[ar*17 + ac + 1] = av.y;
        As[ar*17 + ac + 2] = av.z;
        As[ar*17 + ac + 3] = av.w;
        *(float4*)&Ws[wr*64 + wc] = wv;
        __syncthreads();
#pragma unroll
        for (int kk = 0; kk < 16; kk++) {
            float a0 = As[(ty*4+0)*17 + kk];
            float a1 = As[(ty*4+1)*17 + kk];
            float a2 = As[(ty*4+2)*17 + kk];
            float a3 = As[(ty*4+3)*17 + kk];
            float4 bv = *(const float4*)&Ws[kk*64 + tx*4];
            c[0][0] += a0*bv.x; c[0][1] += a0*bv.y; c[0][2] += a0*bv.z; c[0][3] += a0*bv.w;
            c[1][0] += a1*bv.x; c[1][1] += a1*bv.y; c[1][2] += a1*bv.z; c[1][3] += a1*bv.w;
            c[2][0] += a2*bv.x; c[2][1] += a2*bv.y; c[2][2] += a2*bv.z; c[2][3] += a2*bv.w;
            c[3][0] += a3*bv.x; c[3][1] += a3*bv.y; c[3][2] += a3*bv.z; c[3][3] += a3*bv.w;
        }
    }

    if (split) {
        const int h = (int)blockIdx.y;
#pragma unroll
        for (int i = 0; i < 4; i++) {
            int m = m0 + ty*4 + i;
            int b = m >> 12, s = m & 4095;
            __half2 lo = __floats2half2_rn(c[i][0], c[i][1]);
            __half2 hi = __floats2half2_rn(c[i][2], c[i][3]);
            uint2 pk;
            pk.x = *(unsigned*)&lo;
            pk.y = *(unsigned*)&hi;
            *(uint2*)(Ch + ((size_t)((b*HH + h)*SS + s))*DKK + tx*4) = pk;
        }
    } else {
#pragma unroll
        for (int i = 0; i < 4; i++) {
            int m = m0 + ty*4 + i;
            float4 o = make_float4(c[i][0], c[i][1], c[i][2], c[i][3]);
            *(float4*)(Cf + (size_t)m*512 + n0 + tx*4) = o;
        }
    }
}

// ---------------------------------------------------------------------------
// fp16 tensor-core flash attention.
// Grid: (S/64, B*H). 128 threads (4 warps). Tile 64q x 64k.
// Warp w owns q-rows [w*16, w*16+16) for full 64 cols -> no cross-warp softmax.
// mma.m16n8k16 f16->f32; P kept in registers (C-frag == A-frag after packing).
// ---------------------------------------------------------------------------
__device__ __forceinline__ int swoff(int r, int c) {   // offset in halves
    return r*64 + ((((c >> 3) ^ (r & 7)) << 3) | (c & 7));
}

__device__ __forceinline__ void cpa16(void* dst, const void* src) {
    unsigned d = (unsigned)__cvta_generic_to_shared(dst);
    asm volatile("cp.async.cg.shared.global [%0], [%1], 16;\n" :: "r"(d), "l"(src) : "memory");
}

#define MMA16816(C, A, B0, B1)                                              \
    asm volatile("mma.sync.aligned.m16n8k16.row.col.f32.f16.f16.f32 "       \
        "{%0,%1,%2,%3}, {%4,%5,%6,%7}, {%8,%9}, {%0,%1,%2,%3};"             \
        : "+f"(C[0]), "+f"(C[1]), "+f"(C[2]), "+f"(C[3])                    \
        : "r"(A[0]), "r"(A[1]), "r"(A[2]), "r"(A[3]), "r"(B0), "r"(B1))

#define LDMX4(R0,R1,R2,R3,ADDR)                                             \
    asm volatile("ldmatrix.sync.aligned.m8n8.x4.shared.b16 {%0,%1,%2,%3}, [%4];" \
        : "=r"(R0), "=r"(R1), "=r"(R2), "=r"(R3) : "r"(ADDR))

#define LDMX4T(R0,R1,R2,R3,ADDR)                                            \
    asm volatile("ldmatrix.sync.aligned.m8n8.x4.trans.shared.b16 {%0,%1,%2,%3}, [%4];" \
        : "=r"(R0), "=r"(R1), "=r"(R2), "=r"(R3) : "r"(ADDR))

__device__ __forceinline__ unsigned f2h2(float a, float b) {
    __half2 h = __floats2half2_rn(a, b);
    return *(unsigned*)&h;
}

__global__ __launch_bounds__(128) void flash_attn_h(
    const __half* __restrict__ Qh, const __half* __restrict__ Kh,
    const __half* __restrict__ Vh, const unsigned* __restrict__ mb,
    float* __restrict__ X)
{
    __shared__ __half Qs[64*64];
    __shared__ __half Ks[2][64*64];
    __shared__ __half Vs[2][64*64];

    const int qt = blockIdx.x, bh = blockIdx.y;
    const int b = bh >> 3, h = bh & 7;
    const __half* Qp = Qh + ((size_t)bh*SS + qt*64)*DKK;
    const __half* Kp = Kh + (size_t)bh*SS*DKK;
    const __half* Vp = Vh + (size_t)bh*SS*DKK;
    const unsigned* mrow = mb + ((size_t)b*SS + qt*64)*SWW;

    const int tid = threadIdx.x;
    const int wid = tid >> 5, lane = tid & 31;
    const int g = lane >> 2, qq = lane & 3;
    const int wr0 = wid * 16;
    const int sub = lane >> 3;

    // ---- load Q tile into swizzled smem ----
#pragma unroll
    for (int it = 0; it < 4; it++) {
        int idx = tid + it*128;              // 512 16B-chunks
        int r = idx >> 3, ch = idx & 7;
        uint4 v = *(const uint4*)(Qp + (size_t)r*DKK + ch*8);
        *(uint4*)(&Qs[swoff(r, ch*8)]) = v;
    }
    __syncthreads();

    // ---- hoist Q A-fragments for all 4 k-steps (Q reused every k-tile) ----
    unsigned aq[4][4];
    {
        int arow = wr0 + (lane & 7) + ((sub & 1) << 3);
#pragma unroll
        for (int ks = 0; ks < 4; ks++) {
            int acol = ks*16 + ((sub >> 1) << 3);
            unsigned ad = (unsigned)__cvta_generic_to_shared(&Qs[swoff(arow, acol)]);
            LDMX4(aq[ks][0], aq[ks][1], aq[ks][2], aq[ks][3], ad);
        }
    }

    float sf[8][4], of[8][4];
    float mx[2] = {-1e30f, -1e30f}, ls[2] = {0.f, 0.f};
#pragma unroll
    for (int j = 0; j < 8; j++)
#pragma unroll
        for (int c = 0; c < 4; c++) of[j][c] = 0.f;

    const float scale = 0.125f;  // 1/sqrt(64)

    // ldmatrix lane geometry
    const int krow_l = (lane & 7) + ((sub >> 1) << 3);  // K (non-trans)
    const int kcol_l = (sub & 1) << 3;
    const int vrow_l = (lane & 7) + ((sub & 1) << 3);   // V (trans)
    const int vcol_l = (sub >> 1) << 3;

    // prologue: prefetch k-tile 0
#pragma unroll
    for (int it = 0; it < 4; it++) {
        int idx = tid + it*128;
        int r = idx >> 3, ch = idx & 7;
        cpa16(&Ks[0][swoff(r, ch*8)], Kp + (size_t)r*DKK + ch*8);
        cpa16(&Vs[0][swoff(r, ch*8)], Vp + (size_t)r*DKK + ch*8);
    }
    asm volatile("cp.async.commit_group;" ::: "memory");

    for (int kt = 0; kt < SS/64; kt++) {
        const int buf = kt & 1;
        if (kt + 1 < SS/64) {
#pragma unroll
            for (int it = 0; it < 4; it++) {
                int idx = tid + it*128;
                int r = idx >> 3, ch = idx & 7;
                size_t go = (size_t)((kt+1)*64 + r)*DKK + ch*8;
                cpa16(&Ks[buf^1][swoff(r, ch*8)], Kp + go);
                cpa16(&Vs[buf^1][swoff(r, ch*8)], Vp + go);
            }
            asm volatile("cp.async.commit_group;" ::: "memory");
            asm volatile("cp.async.wait_group 1;" ::: "memory");
        } else {
            asm volatile("cp.async.wait_group 0;" ::: "memory");
        }
        __syncthreads();

        // ---- S = Q K^T ----
#pragma unroll
        for (int j = 0; j < 8; j++)
#pragma unroll
            for (int c = 0; c < 4; c++) sf[j][c] = 0.f;

#pragma unroll
        for (int ks = 0; ks < 4; ks++) {
            int k0 = ks*16;
#pragma unroll
            for (int np = 0; np < 4; np++) {
                unsigned b0, b1, b2, b3;
                unsigned ad = (unsigned)__cvta_generic_to_shared(
                    &Ks[buf][swoff(16*np + krow_l, k0 + kcol_l)]);
                LDMX4(b0, b1, b2, b3, ad);
                MMA16816(sf[2*np],   aq[ks], b0, b1);
                MMA16816(sf[2*np+1], aq[ks], b2, b3);
            }
        }

        // ---- mask + online softmax (rows wr0+g, wr0+g+8) ----
#pragma unroll
        for (int hh = 0; hh < 2; hh++) {
            int row = wr0 + g + hh*8;
            unsigned w0 = mrow[row*SWW + kt*2];
            unsigned w1 = mrow[row*SWW + kt*2 + 1];
            float rmax = -1e30f;
#pragma unroll
            for (int j = 0; j < 8; j++) {
                unsigned w = (j < 4) ? w0 : w1;
                int base = ((j & 3) << 3) + 2*qq;
                float s0 = ((w >> base)     & 1u) ? sf[j][hh*2]  *scale : -1e9f;
                float s1 = ((w >> (base+1)) & 1u) ? sf[j][hh*2+1]*scale : -1e9f;
                sf[j][hh*2] = s0; sf[j][hh*2+1] = s1;
                rmax = fmaxf(rmax, fmaxf(s0, s1));
            }
            rmax = fmaxf(rmax, __shfl_xor_sync(0xffffffffu, rmax, 1));
            rmax = fmaxf(rmax, __shfl_xor_sync(0xffffffffu, rmax, 2));
            float mnew = fmaxf(mx[hh], rmax);
            float corr = __expf(mx[hh] - mnew);
            mx[hh] = mnew;
            float rs = 0.f;
#pragma unroll
            for (int j = 0; j < 8; j++) {
                float p0 = __expf(sf[j][hh*2]   - mnew);
                float p1 = __expf(sf[j][hh*2+1] - mnew);
                sf[j][hh*2] = p0; sf[j][hh*2+1] = p1;
                rs += p0 + p1;
            }
            rs += __shfl_xor_sync(0xffffffffu, rs, 1);
            rs += __shfl_xor_sync(0xffffffffu, rs, 2);
            ls[hh] = ls[hh]*corr + rs;
#pragma unroll
            for (int j = 0; j < 8; j++) {
                of[j][hh*2]   *= corr;
                of[j][hh*2+1] *= corr;
            }
        }

        // ---- O += P V : P packed in-register (C-frag layout == A-frag) ----
#pragma unroll
        for (int jp = 0; jp < 4; jp++) {
            unsigned pa[4];
            pa[0] = f2h2(sf[2*jp][0],   sf[2*jp][1]);
            pa[1] = f2h2(sf[2*jp][2],   sf[2*jp][3]);
            pa[2] = f2h2(sf[2*jp+1][0], sf[2*jp+1][1]);
            pa[3] = f2h2(sf[2*jp+1][2], sf[2*jp+1][3]);
            int k0 = 16*jp;
#pragma unroll
            for (int dp = 0; dp < 4; dp++) {
                unsigned b0, b1, b2, b3;
                unsigned ad = (unsigned)__cvta_generic_to_shared(
                    &Vs[buf][swoff(k0 + vrow_l, 16*dp + vcol_l)]);
                LDMX4T(b0, b1, b2, b3, ad);
                MMA16816(of[2*dp],   pa, b0, b1);
                MMA16816(of[2*dp+1], pa, b2, b3);
            }
        }
        __syncthreads();
    }

    // ---- epilogue: normalize + write X[b, s, h*64+dk] (fp32) ----
#pragma unroll
    for (int hh = 0; hh < 2; hh++) {
        int row = qt*64 + wr0 + g + hh*8;
        float inv = 1.0f / ls[hh];
        float* Xp = X + ((size_t)(b*SS + row))*DD + h*DKK;
#pragma unroll
        for (int j = 0; j < 8; j++) {
            float2 o = make_float2(of[j][hh*2]*inv, of[j][hh*2+1]*inv);
            *(float2*)(Xp + j*8 + 2*qq) = o;
        }
    }
}

// ---------------------------------------------------------------------------
extern "C" void kernel_launch(void* const* d_in, const int* in_sizes, int n_in,
                              void* d_out, int out_size) {
    const float* q    = (const float*)d_in[0];
    const float* k    = (const float*)d_in[1];
    const float* v    = (const float*)d_in[2];
    const int*   mask = (const int*)  d_in[3];
    const float* wq   = (const float*)d_in[4];
    const float* wk   = (const float*)d_in[5];
    const float* wv   = (const float*)d_in[6];
    const float* wo   = (const float*)d_in[7];
    float* out = (float*)d_out;

    __half *Qh, *Kh, *Vh;
    float *X;
    unsigned* mbp;
    cudaGetSymbolAddress((void**)&Qh,  g_Qh);
    cudaGetSymbolAddress((void**)&Kh,  g_Kh);
    cudaGetSymbolAddress((void**)&Vh,  g_Vh);
    cudaGetSymbolAddress((void**)&X,   g_X);
    cudaGetSymbolAddress((void**)&mbp, g_mbits);

    pack_mask<<<(BB*SS*SS)/256, 256>>>(mask, mbp);

    dim3 gg(MM/64, DD/64);
    gemm512<<<gg, 256>>>(q, wq, nullptr, Qh, 1);
    gemm512<<<gg, 256>>>(k, wk, nullptr, Kh, 1);
    gemm512<<<gg, 256>>>(v, wv, nullptr, Vh, 1);

    flash_attn_h<<<dim3(SS/64, BB*HH), 128>>>(Qh, Kh, Vh, mbp, X);

    gemm512<<<gg, 256>>>(X, wo, out, nullptr, 0);
}

// round 8
// speedup vs baseline: 4.4570x; 1.5467x over previous
#include <cuda_runtime.h>
#include <cuda_fp16.h>

// Problem constants
#define BB 2
#define SS 4096
#define DD 512
#define HH 8
#define DKK 64
#define MM (BB*SS)        // 8192 rows
#define SWW (SS/32)       // 128 mask words per row

// Scratch (device globals; no runtime allocation allowed)
__device__ __half g_Qh[MM*DD];       // head-split [(b*H+h), s, dk], fp16
__device__ __half g_Kh[MM*DD];
__device__ __half g_Vh[MM*DD];
__device__ float  g_X [MM*DD];       // attention output, [b, s, d], fp32
__device__ unsigned g_mbits[BB*SS*SWW];  // bit-packed mask
// split-fp16 staging for tensor-core GEMMs
__device__ __half g_Ahi[MM*DD], g_Alo[MM*DD];
__device__ __half g_Whi[DD*DD], g_Wlo[DD*DD];

// ---------------------------------------------------------------------------
// Pack int32 mask (0/1) into bits
// ---------------------------------------------------------------------------
__global__ __launch_bounds__(256) void pack_mask(const int* __restrict__ mask,
                                                 unsigned* __restrict__ mb) {
    int gid = blockIdx.x * 256 + threadIdx.x;
    int bit = mask[gid] != 0;
    unsigned w = __ballot_sync(0xffffffffu, bit);
    if ((threadIdx.x & 31) == 0) mb[gid >> 5] = w;
}

// ---------------------------------------------------------------------------
// fp32 -> (hi, lo) fp16 split:  x ~= hi + lo, lo error O(u^2)
// ---------------------------------------------------------------------------
__global__ __launch_bounds__(256) void cvt_split(const float* __restrict__ A,
                                                 __half* __restrict__ hi,
                                                 __half* __restrict__ lo) {
    int gid = blockIdx.x * 256 + threadIdx.x;   // one float4 per thread
    float4 a = ((const float4*)A)[gid];
    __half h0 = __float2half_rn(a.x), h1 = __float2half_rn(a.y);
    __half h2 = __float2half_rn(a.z), h3 = __float2half_rn(a.w);
    __half l0 = __float2half_rn(a.x - __half2float(h0));
    __half l1 = __float2half_rn(a.y - __half2float(h1));
    __half l2 = __float2half_rn(a.z - __half2float(h2));
    __half l3 = __float2half_rn(a.w - __half2float(h3));
    __half2 ph0 = __halves2half2(h0, h1), ph1 = __halves2half2(h2, h3);
    __half2 pl0 = __halves2half2(l0, l1), pl1 = __halves2half2(l2, l3);
    uint2 ph, pl;
    ph.x = *(unsigned*)&ph0; ph.y = *(unsigned*)&ph1;
    pl.x = *(unsigned*)&pl0; pl.y = *(unsigned*)&pl1;
    ((uint2*)hi)[gid] = ph;
    ((uint2*)lo)[gid] = pl;
}

// ---------------------------------------------------------------------------
// Shared tensor-core helpers
// ---------------------------------------------------------------------------
__device__ __forceinline__ int swoff(int r, int c) {   // offset in halves, 64-wide rows
    return r*64 + ((((c >> 3) ^ (r & 7)) << 3) | (c & 7));
}

__device__ __forceinline__ void cpa16(void* dst, const void* src) {
    unsigned d = (unsigned)__cvta_generic_to_shared(dst);
    asm volatile("cp.async.cg.shared.global [%0], [%1], 16;\n" :: "r"(d), "l"(src) : "memory");
}

#define MMA16816(C, A, B0, B1)                                              \
    asm volatile("mma.sync.aligned.m16n8k16.row.col.f32.f16.f16.f32 "       \
        "{%0,%1,%2,%3}, {%4,%5,%6,%7}, {%8,%9}, {%0,%1,%2,%3};"             \
        : "+f"(C[0]), "+f"(C[1]), "+f"(C[2]), "+f"(C[3])                    \
        : "r"(A[0]), "r"(A[1]), "r"(A[2]), "r"(A[3]), "r"(B0), "r"(B1))

#define LDMX4(R0,R1,R2,R3,ADDR)                                             \
    asm volatile("ldmatrix.sync.aligned.m8n8.x4.shared.b16 {%0,%1,%2,%3}, [%4];" \
        : "=r"(R0), "=r"(R1), "=r"(R2), "=r"(R3) : "r"(ADDR))

#define LDMX4T(R0,R1,R2,R3,ADDR)                                            \
    asm volatile("ldmatrix.sync.aligned.m8n8.x4.trans.shared.b16 {%0,%1,%2,%3}, [%4];" \
        : "=r"(R0), "=r"(R1), "=r"(R2), "=r"(R3) : "r"(ADDR))

__device__ __forceinline__ unsigned f2h2(float a, float b) {
    __half2 h = __floats2half2_rn(a, b);
    return *(unsigned*)&h;
}

// ---------------------------------------------------------------------------
// Split-fp16 tensor-core GEMM: C[8192x512] = A * W, fp32-accurate via
// C = Ahi*Whi + Ahi*Wlo + Alo*Whi.
// CTA tile 128x64, BK=64, 256 thr / 8 warps (4m x 2n), warp tile 32x32.
// split=1: write half head-split [(b*H+h), s, dk]; split=0: fp32 row-major.
// ---------------------------------------------------------------------------
__device__ __forceinline__ void gemm_load_stage(
    const __half* __restrict__ Ahi_, const __half* __restrict__ Alo_,
    const __half* __restrict__ Whi_, const __half* __restrict__ Wlo_,
    __half* sAhi, __half* sAlo, __half* sWhi, __half* sWlo,
    int m0, int n0, int kc, int tid)
{
#pragma unroll
    for (int it = 0; it < 4; it++) {
        int idx = tid + it*256;
        int r = idx >> 3, ch = idx & 7;
        int so = swoff(r, ch*8);
        size_t ga = (size_t)(m0 + r)*512 + kc*64 + ch*8;
        cpa16(sAhi + so, Ahi_ + ga);
        cpa16(sAlo + so, Alo_ + ga);
    }
#pragma unroll
    for (int it = 0; it < 2; it++) {
        int idx = tid + it*256;
        int r = idx >> 3, ch = idx & 7;
        int so = swoff(r, ch*8);
        size_t gw = (size_t)(kc*64 + r)*512 + n0 + ch*8;
        cpa16(sWhi + so, Whi_ + gw);
        cpa16(sWlo + so, Wlo_ + gw);
    }
}

__global__ __launch_bounds__(256) void gemm_tc(
    const __half* __restrict__ Ahi_, const __half* __restrict__ Alo_,
    const __half* __restrict__ Whi_, const __half* __restrict__ Wlo_,
    float* __restrict__ Cf, __half* __restrict__ Ch, int split)
{
    extern __shared__ __half sm_[];
    __half* sAhi = sm_;                    // 2 x 128*64
    __half* sAlo = sAhi + 2*128*64;
    __half* sWhi = sAlo + 2*128*64;        // 2 x 64*64
    __half* sWlo = sWhi + 2*64*64;

    const int m0 = blockIdx.x * 128;
    const int n0 = blockIdx.y * 64;
    const int tid = threadIdx.x;
    const int wid = tid >> 5, lane = tid & 31;
    const int wm = (wid >> 1) * 32, wn = (wid & 1) * 32;
    const int g = lane >> 2, qq = lane & 3, sub = lane >> 3;

    float c[2][4][4];
#pragma unroll
    for (int mf = 0; mf < 2; mf++)
#pragma unroll
        for (int j = 0; j < 4; j++)
#pragma unroll
            for (int e = 0; e < 4; e++) c[mf][j][e] = 0.f;

    gemm_load_stage(Ahi_, Alo_, Whi_, Wlo_, sAhi, sAlo, sWhi, sWlo, m0, n0, 0, tid);
    asm volatile("cp.async.commit_group;" ::: "memory");

    const int arow_l = (lane & 7) + ((sub & 1) << 3);
    const int acol_l = (sub >> 1) << 3;
    const int brow_l = (lane & 7) + ((sub & 1) << 3);
    const int bcol_l = (sub >> 1) << 3;

    for (int kc = 0; kc < 8; kc++) {
        const int st = kc & 1;
        if (kc + 1 < 8) {
            gemm_load_stage(Ahi_, Alo_, Whi_, Wlo_,
                            sAhi + (st^1)*128*64, sAlo + (st^1)*128*64,
                            sWhi + (st^1)*64*64,  sWlo + (st^1)*64*64,
                            m0, n0, kc + 1, tid);
            asm volatile("cp.async.commit_group;" ::: "memory");
            asm volatile("cp.async.wait_group 1;" ::: "memory");
        } else {
            asm volatile("cp.async.wait_group 0;" ::: "memory");
        }
        __syncthreads();

        const __half* A_hi = sAhi + st*128*64;
        const __half* A_lo = sAlo + st*128*64;
        const __half* W_hi = sWhi + st*64*64;
        const __half* W_lo = sWlo + st*64*64;

#pragma unroll
        for (int ks = 0; ks < 4; ks++) {
            unsigned ahi[2][4], alo[2][4];
#pragma unroll
            for (int mf = 0; mf < 2; mf++) {
                unsigned adh = (unsigned)__cvta_generic_to_shared(
                    &A_hi[swoff(wm + mf*16 + arow_l, ks*16 + acol_l)]);
                LDMX4(ahi[mf][0], ahi[mf][1], ahi[mf][2], ahi[mf][3], adh);
                unsigned adl = (unsigned)__cvta_generic_to_shared(
                    &A_lo[swoff(wm + mf*16 + arow_l, ks*16 + acol_l)]);
                LDMX4(alo[mf][0], alo[mf][1], alo[mf][2], alo[mf][3], adl);
            }
#pragma unroll
            for (int dp = 0; dp < 2; dp++) {
                unsigned h0,h1,h2,h3, l0,l1,l2,l3;
                unsigned bdh = (unsigned)__cvta_generic_to_shared(
                    &W_hi[swoff(ks*16 + brow_l, wn + dp*16 + bcol_l)]);
                LDMX4T(h0, h1, h2, h3, bdh);
                unsigned bdl = (unsigned)__cvta_generic_to_shared(
                    &W_lo[swoff(ks*16 + brow_l, wn + dp*16 + bcol_l)]);
                LDMX4T(l0, l1, l2, l3, bdl);
#pragma unroll
                for (int mf = 0; mf < 2; mf++) {
                    MMA16816(c[mf][2*dp],   ahi[mf], h0, h1);
                    MMA16816(c[mf][2*dp+1], ahi[mf], h2, h3);
                    MMA16816(c[mf][2*dp],   ahi[mf], l0, l1);
                    MMA16816(c[mf][2*dp+1], ahi[mf], l2, l3);
                    MMA16816(c[mf][2*dp],   alo[mf], h0, h1);
                    MMA16816(c[mf][2*dp+1], alo[mf], h2, h3);
                }
            }
        }
        __syncthreads();
    }

    // Epilogue. C frag (mf, j): rows {g, g+8} of [wm+mf*16 ..), cols wn + j*8 + {2q, 2q+1}
    if (split) {
        const int h = (int)blockIdx.y;
#pragma unroll
        for (int mf = 0; mf < 2; mf++)
#pragma unroll
            for (int rr = 0; rr < 2; rr++) {
                int m = m0 + wm + mf*16 + g + rr*8;
                int b = m >> 12, s = m & 4095;
                __half* dst = Ch + ((size_t)((b*HH + h)*SS + s))*DKK;
#pragma unroll
                for (int j = 0; j < 4; j++) {
                    __half2 o = __floats2half2_rn(c[mf][j][rr*2], c[mf][j][rr*2+1]);
                    *(__half2*)(dst + wn + j*8 + 2*qq) = o;
                }
            }
    } else {
#pragma unroll
        for (int mf = 0; mf < 2; mf++)
#pragma unroll
            for (int rr = 0; rr < 2; rr++) {
                int m = m0 + wm + mf*16 + g + rr*8;
                float* dst = Cf + (size_t)m*512 + n0;
#pragma unroll
                for (int j = 0; j < 4; j++) {
                    float2 o = make_float2(c[mf][j][rr*2], c[mf][j][rr*2+1]);
                    *(float2*)(dst + wn + j*8 + 2*qq) = o;
                }
            }
    }
}

// ---------------------------------------------------------------------------
// fp16 tensor-core flash attention (unchanged from R5).
// Grid: (S/64, B*H). 128 threads (4 warps). Tile 64q x 64k.
// ---------------------------------------------------------------------------
__global__ __launch_bounds__(128) void flash_attn_h(
    const __half* __restrict__ Qh, const __half* __restrict__ Kh,
    const __half* __restrict__ Vh, const unsigned* __restrict__ mb,
    float* __restrict__ X)
{
    __shared__ __half Qs[64*64];
    __shared__ __half Ks[2][64*64];
    __shared__ __half Vs[2][64*64];

    const int qt = blockIdx.x, bh = blockIdx.y;
    const int b = bh >> 3, h = bh & 7;
    const __half* Qp = Qh + ((size_t)bh*SS + qt*64)*DKK;
    const __half* Kp = Kh + (size_t)bh*SS*DKK;
    const __half* Vp = Vh + (size_t)bh*SS*DKK;
    const unsigned* mrow = mb + ((size_t)b*SS + qt*64)*SWW;

    const int tid = threadIdx.x;
    const int wid = tid >> 5, lane = tid & 31;
    const int g = lane >> 2, qq = lane & 3;
    const int wr0 = wid * 16;
    const int sub = lane >> 3;

#pragma unroll
    for (int it = 0; it < 4; it++) {
        int idx = tid + it*128;
        int r = idx >> 3, ch = idx & 7;
        uint4 v = *(const uint4*)(Qp + (size_t)r*DKK + ch*8);
        *(uint4*)(&Qs[swoff(r, ch*8)]) = v;
    }
    __syncthreads();

    unsigned aq[4][4];
    {
        int arow = wr0 + (lane & 7) + ((sub & 1) << 3);
#pragma unroll
        for (int ks = 0; ks < 4; ks++) {
            int acol = ks*16 + ((sub >> 1) << 3);
            unsigned ad = (unsigned)__cvta_generic_to_shared(&Qs[swoff(arow, acol)]);
            LDMX4(aq[ks][0], aq[ks][1], aq[ks][2], aq[ks][3], ad);
        }
    }

    float sf[8][4], of[8][4];
    float mx[2] = {-1e30f, -1e30f}, ls[2] = {0.f, 0.f};
#pragma unroll
    for (int j = 0; j < 8; j++)
#pragma unroll
        for (int c = 0; c < 4; c++) of[j][c] = 0.f;

    const float scale = 0.125f;

    const int krow_l = (lane & 7) + ((sub >> 1) << 3);
    const int kcol_l = (sub & 1) << 3;
    const int vrow_l = (lane & 7) + ((sub & 1) << 3);
    const int vcol_l = (sub >> 1) << 3;

#pragma unroll
    for (int it = 0; it < 4; it++) {
        int idx = tid + it*128;
        int r = idx >> 3, ch = idx & 7;
        cpa16(&Ks[0][swoff(r, ch*8)], Kp + (size_t)r*DKK + ch*8);
        cpa16(&Vs[0][swoff(r, ch*8)], Vp + (size_t)r*DKK + ch*8);
    }
    asm volatile("cp.async.commit_group;" ::: "memory");

    for (int kt = 0; kt < SS/64; kt++) {
        const int buf = kt & 1;
        if (kt + 1 < SS/64) {
#pragma unroll
            for (int it = 0; it < 4; it++) {
                int idx = tid + it*128;
                int r = idx >> 3, ch = idx & 7;
                size_t go = (size_t)((kt+1)*64 + r)*DKK + ch*8;
                cpa16(&Ks[buf^1][swoff(r, ch*8)], Kp + go);
                cpa16(&Vs[buf^1][swoff(r, ch*8)], Vp + go);
            }
            asm volatile("cp.async.commit_group;" ::: "memory");
            asm volatile("cp.async.wait_group 1;" ::: "memory");
        } else {
            asm volatile("cp.async.wait_group 0;" ::: "memory");
        }
        __syncthreads();

#pragma unroll
        for (int j = 0; j < 8; j++)
#pragma unroll
            for (int c = 0; c < 4; c++) sf[j][c] = 0.f;

#pragma unroll
        for (int ks = 0; ks < 4; ks++) {
            int k0 = ks*16;
#pragma unroll
            for (int np = 0; np < 4; np++) {
                unsigned b0, b1, b2, b3;
                unsigned ad = (unsigned)__cvta_generic_to_shared(
                    &Ks[buf][swoff(16*np + krow_l, k0 + kcol_l)]);
                LDMX4(b0, b1, b2, b3, ad);
                MMA16816(sf[2*np],   aq[ks], b0, b1);
                MMA16816(sf[2*np+1], aq[ks], b2, b3);
            }
        }

#pragma unroll
        for (int hh = 0; hh < 2; hh++) {
            int row = wr0 + g + hh*8;
            unsigned w0 = mrow[row*SWW + kt*2];
            unsigned w1 = mrow[row*SWW + kt*2 + 1];
            float rmax = -1e30f;
#pragma unroll
            for (int j = 0; j < 8; j++) {
                unsigned w = (j < 4) ? w0 : w1;
                int base = ((j & 3) << 3) + 2*qq;
                float s0 = ((w >> base)     & 1u) ? sf[j][hh*2]  *scale : -1e9f;
                float s1 = ((w >> (base+1)) & 1u) ? sf[j][hh*2+1]*scale : -1e9f;
                sf[j][hh*2] = s0; sf[j][hh*2+1] = s1;
                rmax = fmaxf(rmax, fmaxf(s0, s1));
            }
            rmax = fmaxf(rmax, __shfl_xor_sync(0xffffffffu, rmax, 1));
            rmax = fmaxf(rmax, __shfl_xor_sync(0xffffffffu, rmax, 2));
            float mnew = fmaxf(mx[hh], rmax);
            float corr = __expf(mx[hh] - mnew);
            mx[hh] = mnew;
            float rs = 0.f;
#pragma unroll
            for (int j = 0; j < 8; j++) {
                float p0 = __expf(sf[j][hh*2]   - mnew);
                float p1 = __expf(sf[j][hh*2+1] - mnew);
                sf[j][hh*2] = p0; sf[j][hh*2+1] = p1;
                rs += p0 + p1;
            }
            rs += __shfl_xor_sync(0xffffffffu, rs, 1);
            rs += __shfl_xor_sync(0xffffffffu, rs, 2);
            ls[hh] = ls[hh]*corr + rs;
#pragma unroll
            for (int j = 0; j < 8; j++) {
                of[j][hh*2]   *= corr;
                of[j][hh*2+1] *= corr;
            }
        }

#pragma unroll
        for (int jp = 0; jp < 4; jp++) {
            unsigned pa[4];
            pa[0] = f2h2(sf[2*jp][0],   sf[2*jp][1]);
            pa[1] = f2h2(sf[2*jp][2],   sf[2*jp][3]);
            pa[2] = f2h2(sf[2*jp+1][0], sf[2*jp+1][1]);
            pa[3] = f2h2(sf[2*jp+1][2], sf[2*jp+1][3]);
            int k0 = 16*jp;
#pragma unroll
            for (int dp = 0; dp < 4; dp++) {
                unsigned b0, b1, b2, b3;
                unsigned ad = (unsigned)__cvta_generic_to_shared(
                    &Vs[buf][swoff(k0 + vrow_l, 16*dp + vcol_l)]);
                LDMX4T(b0, b1, b2, b3, ad);
                MMA16816(of[2*dp],   pa, b0, b1);
                MMA16816(of[2*dp+1], pa, b2, b3);
            }
        }
        __syncthreads();
    }

#pragma unroll
    for (int hh = 0; hh < 2; hh++) {
        int row = qt*64 + wr0 + g + hh*8;
        float inv = 1.0f / ls[hh];
        float* Xp = X + ((size_t)(b*SS + row))*DD + h*DKK;
#pragma unroll
        for (int j = 0; j < 8; j++) {
            float2 o = make_float2(of[j][hh*2]*inv, of[j][hh*2+1]*inv);
            *(float2*)(Xp + j*8 + 2*qq) = o;
        }
    }
}

// ---------------------------------------------------------------------------
extern "C" void kernel_launch(void* const* d_in, const int* in_sizes, int n_in,
                              void* d_out, int out_size) {
    const float* q    = (const float*)d_in[0];
    const float* k    = (const float*)d_in[1];
    const float* v    = (const float*)d_in[2];
    const int*   mask = (const int*)  d_in[3];
    const float* wq   = (const float*)d_in[4];
    const float* wk   = (const float*)d_in[5];
    const float* wv   = (const float*)d_in[6];
    const float* wo   = (const float*)d_in[7];
    float* out = (float*)d_out;

    __half *Qh, *Kh, *Vh, *Ahi, *Alo, *Whi, *Wlo;
    float *X;
    unsigned* mbp;
    cudaGetSymbolAddress((void**)&Qh,  g_Qh);
    cudaGetSymbolAddress((void**)&Kh,  g_Kh);
    cudaGetSymbolAddress((void**)&Vh,  g_Vh);
    cudaGetSymbolAddress((void**)&X,   g_X);
    cudaGetSymbolAddress((void**)&mbp, g_mbits);
    cudaGetSymbolAddress((void**)&Ahi, g_Ahi);
    cudaGetSymbolAddress((void**)&Alo, g_Alo);
    cudaGetSymbolAddress((void**)&Whi, g_Whi);
    cudaGetSymbolAddress((void**)&Wlo, g_Wlo);

    pack_mask<<<(BB*SS*SS)/256, 256>>>(mask, mbp);

    const int FS_G = (2*128*64 + 2*128*64 + 2*64*64 + 2*64*64) * 2;  // 98304 B
    cudaFuncSetAttribute(gemm_tc, cudaFuncAttributeMaxDynamicSharedMemorySize, FS_G);

    const int NA4 = MM*DD/4;   // activation float4 count
    const int NW4 = DD*DD/4;   // weight float4 count
    dim3 gg(MM/128, DD/64);

    // Q projection
    cvt_split<<<NA4/256, 256>>>(q,  Ahi, Alo);
    cvt_split<<<NW4/256, 256>>>(wq, Whi, Wlo);
    gemm_tc<<<gg, 256, FS_G>>>(Ahi, Alo, Whi, Wlo, nullptr, Qh, 1);
    // K projection
    cvt_split<<<NA4/256, 256>>>(k,  Ahi, Alo);
    cvt_split<<<NW4/256, 256>>>(wk, Whi, Wlo);
    gemm_tc<<<gg, 256, FS_G>>>(Ahi, Alo, Whi, Wlo, nullptr, Kh, 1);
    // V projection
    cvt_split<<<NA4/256, 256>>>(v,  Ahi, Alo);
    cvt_split<<<NW4/256, 256>>>(wv, Whi, Wlo);
    gemm_tc<<<gg, 256, FS_G>>>(Ahi, Alo, Whi, Wlo, nullptr, Vh, 1);

    flash_attn_h<<<dim3(SS/64, BB*HH), 128>>>(Qh, Kh, Vh, mbp, X);

    // Output projection
    cvt_split<<<NA4/256, 256>>>(X,  Ahi, Alo);
    cvt_split<<<NW4/256, 256>>>(wo, Whi, Wlo);
    gemm_tc<<<gg, 256, FS_G>>>(Ahi, Alo, Whi, Wlo, out, nullptr, 0);
}